// round 2
// baseline (speedup 1.0000x reference)
#include <cuda_runtime.h>

// out[b,p,:] = { c1*c2*c3, c0*c1, c0*c1*c2, c0*c1*c2*c3 }, c_i = cos(patches[b,p,i]).
// RZ params provably do not affect the output (unit phases cancel in |amp|^2).
//
// R2: 4 float4 per thread, loads front-batched for MLP=4, to cover DRAM latency.

#define ITEMS 4

__global__ __launch_bounds__(256) void quantum_patch_kernel(
    const float4* __restrict__ in,
    float4* __restrict__ out,
    int n_patches) {
    // Block handles a contiguous chunk of 256*ITEMS float4s; thread t takes
    // t, t+256, t+512, t+768 within the chunk (coalesced per-iteration).
    int base = blockIdx.x * (256 * ITEMS) + threadIdx.x;

    float4 x[ITEMS];
    #pragma unroll
    for (int k = 0; k < ITEMS; k++) {
        int idx = base + k * 256;
        if (idx < n_patches) x[k] = in[idx];
    }

    float4 o[ITEMS];
    #pragma unroll
    for (int k = 0; k < ITEMS; k++) {
        float c0 = __cosf(x[k].x);
        float c1 = __cosf(x[k].y);
        float c2 = __cosf(x[k].z);
        float c3 = __cosf(x[k].w);
        float c01  = c0 * c1;
        float c012 = c01 * c2;
        o[k].x = c1 * c2 * c3;
        o[k].y = c01;
        o[k].z = c012;
        o[k].w = c012 * c3;
    }

    #pragma unroll
    for (int k = 0; k < ITEMS; k++) {
        int idx = base + k * 256;
        if (idx < n_patches) out[idx] = o[k];
    }
}

extern "C" void kernel_launch(void* const* d_in, const int* in_sizes, int n_in,
                              void* d_out, int out_size) {
    const float4* patches = (const float4*)d_in[0];   // (256, 2048, 4) f32
    float4* out = (float4*)d_out;                     // (256, 8192) f32 — same layout
    int n_patches = in_sizes[0] / 4;                  // 524288
    int threads = 256;
    int per_block = threads * ITEMS;
    int blocks = (n_patches + per_block - 1) / per_block;  // 512
    quantum_patch_kernel<<<blocks, threads>>>(patches, out, n_patches);
}